// round 4
// baseline (speedup 1.0000x reference)
#include <cuda_runtime.h>
#include <math.h>

// Problem constants (fixed by the reference)
#define BB    4096
#define AA    3
#define HH    13
#define WW    13
#define CC    5
#define NT    32
#define CH    (5 + CC)          // 10 channels per anchor
#define HW    (HH * WW)         // 169
#define NCELL (AA * HW)         // 507

// Per-batch partial results: [obj_b, bbox_b, cls_b] per batch.
__device__ float g_scratch[BB * 3];
__device__ unsigned int g_done = 0;   // last-block counter (reset by last block each run)

__device__ __forceinline__ float bce_logits(float x, float t) {
    // max(x,0) - x*t + softplus(-|x|)
    return fmaxf(x, 0.0f) - x * t + log1pf(expf(-fabsf(x)));
}

__global__ void __launch_bounds__(256)
sgs_loss_fused(const float* __restrict__ pred,
               const float* __restrict__ tboxes,
               const long long* __restrict__ tlabels,
               const float* __restrict__ anchors,
               float* __restrict__ out, int B)
{
    __shared__ int    s_win[NCELL];      // last-wins winner (bbox/obj scatter)
    __shared__ int    s_win_cls[NCELL];  // last-wins winner (cls scatter)
    __shared__ float  s_tbox[NT][4];
    __shared__ int    s_lab[NT];
    __shared__ float  s_red[8][5];
    __shared__ int    s_plist[NT];       // packed positive cells (canonical order)
    __shared__ int    s_npos;
    __shared__ int    s_islast;
    __shared__ double s_dred[8][3];

    const int b   = blockIdx.x;
    const int tid = threadIdx.x;

    for (int i = tid; i < NCELL; i += 256) { s_win[i] = -1; s_win_cls[i] = -1; }
    if (tid == 0) s_npos = 0;
    __syncthreads();

    // ---- per-target processing (threads 0..31) ----
    if (tid < NT) {
        float4 box = ((const float4*)tboxes)[b * NT + tid];
        float cx = box.x, cy = box.y, w = box.z, h = box.w;
        bool valid = (cx > 0.0f) && (cx < 1.0f) && (cy > 0.0f) && (cy < 1.0f)
                  && (w > 0.0f) && (h > 0.0f);
        float ws = valid ? w : 1.0f;
        float hs = valid ? h : 1.0f;
        int gx = (int)(cx * (float)WW); gx = min(max(gx, 0), WW - 1);
        int gy = (int)(cy * (float)HH); gy = min(max(gy, 0), HH - 1);

        // argmax IoU over anchors (first occurrence on ties, matching jnp.argmax)
        int   besta = 0;
        float bestiou = -1.0f, baw = 1.0f, bah = 1.0f;
        #pragma unroll
        for (int a = 0; a < AA; a++) {
            float aw = anchors[a * 2 + 0];
            float ah = anchors[a * 2 + 1];
            float inter = fminf(ws, aw) * fminf(hs, ah);
            float iou = inter / (ws * hs + aw * ah - inter);
            if (iou > bestiou) { bestiou = iou; besta = a; baw = aw; bah = ah; }
        }

        s_tbox[tid][0] = cx * (float)WW - (float)gx;
        s_tbox[tid][1] = cy * (float)HH - (float)gy;
        s_tbox[tid][2] = logf(ws / baw + 1e-16f);
        s_tbox[tid][3] = logf(hs / bah + 1e-16f);

        long long lb = tlabels[b * NT + tid];
        bool labok = (lb >= 0) && (lb < (long long)CC);
        long long lc = lb < 0 ? 0 : (lb > (long long)(CC - 1) ? (long long)(CC - 1) : lb);
        s_lab[tid] = (int)lc;

        if (valid) {
            int cell = besta * HW + gy * WW + gx;
            atomicMax(&s_win[cell], tid);          // last-update-wins
            if (labok) atomicMax(&s_win_cls[cell], tid);
        }
    }
    __syncthreads();

    // ---- deterministic positive-cell compaction (warp 0, canonical cell order) ----
    if (tid < 32) {
        int base = 0;
        for (int c0 = 0; c0 < NCELL; c0 += 32) {
            int cell = c0 + tid;
            int wg = (cell < NCELL) ? s_win[cell] : -1;
            unsigned bal = __ballot_sync(0xFFFFFFFFu, wg >= 0);
            if (wg >= 0) {
                int slot = base + __popc(bal & ((1u << tid) - 1u));
                int wc = s_win_cls[cell];
                int lb = (wc >= 0) ? s_lab[wc] : -1;
                // pack: cell [0:10), wg [10:15), lb+1 [15:18)
                s_plist[slot] = cell | (wg << 10) | ((lb + 1) << 15);
            }
            base += __popc(bal);
        }
        if (tid == 0) s_npos = base;
    }

    // ---- pass A: objectness BCE over all 507 cells (contiguous loads) ----
    float neg = 0.0f, pos = 0.0f;
    int   cnt = 0;
    const float* pb = pred + (size_t)b * (AA * CH * HW);

    for (int cidx = tid; cidx < NCELL; cidx += 256) {
        int a  = cidx / HW;
        int hw = cidx - a * HW;
        float po = pb[a * CH * HW + hw];
        if (s_win[cidx] < 0) {
            neg += bce_logits(po, 0.0f);
        } else {
            pos += bce_logits(po, 1.0f);
            cnt++;
        }
    }
    __syncthreads();

    // ---- pass B: positive-cell bbox + cls, distributed for MLP ----
    float bsum = 0.0f, csum = 0.0f;
    const int npos9 = s_npos * 9;
    for (int idx = tid; idx < npos9; idx += 256) {
        int p = idx / 9;
        int j = idx - p * 9;
        int e    = s_plist[p];
        int cell = e & 1023;
        int wg   = (e >> 10) & 31;
        int lb   = ((e >> 15) & 7) - 1;
        int a    = cell / HW;
        int hw   = cell - a * HW;
        float val = pb[a * CH * HW + (1 + j) * HW + hw];
        if (j < 4) {
            float d = val - s_tbox[wg][j];
            bsum += d * d;
        } else {
            int c = j - 4;
            csum += bce_logits(val, (c == lb) ? 1.0f : 0.0f);
        }
    }

    // ---- block reduction of {neg, pos, bsum, csum, cnt} ----
    float v[5] = {neg, pos, bsum, csum, (float)cnt};
    #pragma unroll
    for (int o = 16; o > 0; o >>= 1) {
        #pragma unroll
        for (int k = 0; k < 5; k++) v[k] += __shfl_down_sync(0xFFFFFFFFu, v[k], o);
    }
    int wid = tid >> 5, lid = tid & 31;
    if (lid == 0) {
        #pragma unroll
        for (int k = 0; k < 5; k++) s_red[wid][k] = v[k];
    }
    __syncthreads();

    if (tid == 0) {
        float rn = 0, rp = 0, rb = 0, rc = 0, rcnt = 0;
        #pragma unroll
        for (int w2 = 0; w2 < 8; w2++) {
            rn += s_red[w2][0]; rp += s_red[w2][1]; rb += s_red[w2][2];
            rc += s_red[w2][3]; rcnt += s_red[w2][4];
        }
        float npos = rcnt;
        float pw = ((float)NCELL - npos) / (npos + 1e-16f);
        float obj_b  = (rn + pw * rp) / (float)NCELL;
        float bbox_b = (npos > 0.0f) ? rb / (4.0f * npos + 1e-30f) : 0.0f;
        float cls_b  = (npos > 0.0f) ? rc / ((float)CC * npos + 1e-30f) : 0.0f;
        g_scratch[b * 3 + 0] = obj_b;
        g_scratch[b * 3 + 1] = bbox_b;
        g_scratch[b * 3 + 2] = cls_b;
    }

    // ---- last-block final reduction (L2-hot scratch, no extra launch) ----
    __threadfence();
    if (tid == 0) {
        unsigned int t = atomicAdd(&g_done, 1u);
        s_islast = (t == (unsigned int)(gridDim.x - 1)) ? 1 : 0;
    }
    __syncthreads();
    if (!s_islast) return;

    double o = 0.0, bb = 0.0, cl = 0.0;
    for (int i = tid; i < B; i += 256) {
        o  += (double)g_scratch[i * 3 + 0];
        bb += (double)g_scratch[i * 3 + 1];
        cl += (double)g_scratch[i * 3 + 2];
    }
    #pragma unroll
    for (int off = 16; off > 0; off >>= 1) {
        o  += __shfl_down_sync(0xFFFFFFFFu, o,  off);
        bb += __shfl_down_sync(0xFFFFFFFFu, bb, off);
        cl += __shfl_down_sync(0xFFFFFFFFu, cl, off);
    }
    if (lid == 0) { s_dred[wid][0] = o; s_dred[wid][1] = bb; s_dred[wid][2] = cl; }
    __syncthreads();
    if (tid == 0) {
        double ro = 0.0, rb = 0.0, rc = 0.0;
        #pragma unroll
        for (int w2 = 0; w2 < 8; w2++) {
            ro += s_dred[w2][0]; rb += s_dred[w2][1]; rc += s_dred[w2][2];
        }
        float objf  = (float)(ro / (double)B);
        float bboxf = (float)(rb / (double)B);
        float clsf  = (float)(rc / (double)B);
        out[0] = 2.0f * objf + 5.0f * bboxf + 2.0f * clsf;
        out[1] = objf;
        out[2] = bboxf;
        out[3] = clsf;
        g_done = 0;   // reset for next graph replay (deterministic across launches)
    }
}

extern "C" void kernel_launch(void* const* d_in, const int* in_sizes, int n_in,
                              void* d_out, int out_size)
{
    const float*     pred    = (const float*)d_in[0];
    const float*     tboxes  = (const float*)d_in[1];
    const long long* tlabels = (const long long*)d_in[2];
    const float*     anchors = (const float*)d_in[3];
    float*           out     = (float*)d_out;

    int B = in_sizes[0] / (AA * CH * HW);
    if (B > BB) B = BB;

    sgs_loss_fused<<<B, 256>>>(pred, tboxes, tlabels, anchors, out, B);
}

// round 5
// speedup vs baseline: 1.5610x; 1.5610x over previous
#include <cuda_runtime.h>
#include <math.h>

// Problem constants (fixed by the reference)
#define BB    4096
#define AA    3
#define HH    13
#define WW    13
#define CC    5
#define NT    32
#define CH    (5 + CC)          // 10 channels per anchor
#define HW    (HH * WW)         // 169
#define NCELL (AA * HW)         // 507

// Per-batch partial results, SoA for coalesced reduce.
__device__ float g_obj[BB];
__device__ float g_bbox[BB];
__device__ float g_cls[BB];

__device__ __forceinline__ float bce_logits_fast(float x, float t) {
    // max(x,0) - x*t + softplus(-|x|); fast-math softplus (abs err < 1e-7)
    return fmaxf(x, 0.0f) - x * t + __logf(1.0f + __expf(-fabsf(x)));
}

__global__ void __launch_bounds__(256)
sgs_loss_per_batch(const float* __restrict__ pred,
                   const float* __restrict__ tboxes,
                   const long long* __restrict__ tlabels,
                   const float* __restrict__ anchors)
{
    __shared__ int   s_win[NCELL];      // last-wins winner (bbox/obj scatter)
    __shared__ int   s_win_cls[NCELL];  // last-wins winner (cls scatter)
    __shared__ float s_tbox[NT][4];
    __shared__ int   s_lab[NT];
    __shared__ float s_red[8][5];

    const int b   = blockIdx.x;
    const int tid = threadIdx.x;

    for (int i = tid; i < NCELL; i += 256) { s_win[i] = -1; s_win_cls[i] = -1; }
    __syncthreads();

    // ---- per-target processing (threads 0..31) ----
    if (tid < NT) {
        float4 box = ((const float4*)tboxes)[b * NT + tid];
        float cx = box.x, cy = box.y, w = box.z, h = box.w;
        bool valid = (cx > 0.0f) && (cx < 1.0f) && (cy > 0.0f) && (cy < 1.0f)
                  && (w > 0.0f) && (h > 0.0f);
        float ws = valid ? w : 1.0f;
        float hs = valid ? h : 1.0f;
        int gx = (int)(cx * (float)WW); gx = min(max(gx, 0), WW - 1);
        int gy = (int)(cy * (float)HH); gy = min(max(gy, 0), HH - 1);

        // argmax IoU over anchors (first occurrence on ties, matching jnp.argmax)
        int   besta = 0;
        float bestiou = -1.0f, baw = 1.0f, bah = 1.0f;
        #pragma unroll
        for (int a = 0; a < AA; a++) {
            float aw = anchors[a * 2 + 0];
            float ah = anchors[a * 2 + 1];
            float inter = fminf(ws, aw) * fminf(hs, ah);
            float iou = inter / (ws * hs + aw * ah - inter);
            if (iou > bestiou) { bestiou = iou; besta = a; baw = aw; bah = ah; }
        }

        s_tbox[tid][0] = cx * (float)WW - (float)gx;
        s_tbox[tid][1] = cy * (float)HH - (float)gy;
        s_tbox[tid][2] = logf(ws / baw + 1e-16f);   // precise (feeds squared loss)
        s_tbox[tid][3] = logf(hs / bah + 1e-16f);

        long long lb = tlabels[b * NT + tid];
        bool labok = (lb >= 0) && (lb < (long long)CC);
        long long lc = lb < 0 ? 0 : (lb > (long long)(CC - 1) ? (long long)(CC - 1) : lb);
        s_lab[tid] = (int)lc;

        if (valid) {
            int cell = besta * HW + gy * WW + gx;
            atomicMax(&s_win[cell], tid);          // last-update-wins
            if (labok) atomicMax(&s_win_cls[cell], tid);
        }
    }
    __syncthreads();

    // ---- main loss loop over 507 cells ----
    float neg = 0.0f, pos = 0.0f, bsum = 0.0f, csum = 0.0f;
    int   cnt = 0;
    const float* pb = pred + (size_t)b * (AA * CH * HW);

    for (int cidx = tid; cidx < NCELL; cidx += 256) {
        int a  = cidx / HW;
        int hw = cidx - a * HW;
        const float* cp = pb + a * CH * HW + hw;

        float po = cp[0];
        int wg = s_win[cidx];
        if (wg < 0) {
            neg += bce_logits_fast(po, 0.0f);
        } else {
            pos += bce_logits_fast(po, 1.0f);
            cnt++;
            #pragma unroll
            for (int j = 0; j < 4; j++) {
                float d = cp[(1 + j) * HW] - s_tbox[wg][j];
                bsum += d * d;
            }
            int wc = s_win_cls[cidx];
            int lb = (wc >= 0) ? s_lab[wc] : -1;
            #pragma unroll
            for (int c = 0; c < CC; c++) {
                csum += bce_logits_fast(cp[(5 + c) * HW], (c == lb) ? 1.0f : 0.0f);
            }
        }
    }

    // ---- block reduction of {neg, pos, bsum, csum, cnt} ----
    float v[5] = {neg, pos, bsum, csum, (float)cnt};
    #pragma unroll
    for (int o = 16; o > 0; o >>= 1) {
        #pragma unroll
        for (int k = 0; k < 5; k++) v[k] += __shfl_down_sync(0xFFFFFFFFu, v[k], o);
    }
    int wid = tid >> 5, lid = tid & 31;
    if (lid == 0) {
        #pragma unroll
        for (int k = 0; k < 5; k++) s_red[wid][k] = v[k];
    }
    __syncthreads();

    if (tid == 0) {
        float rn = 0, rp = 0, rb = 0, rc = 0, rcnt = 0;
        #pragma unroll
        for (int w2 = 0; w2 < 8; w2++) {
            rn += s_red[w2][0]; rp += s_red[w2][1]; rb += s_red[w2][2];
            rc += s_red[w2][3]; rcnt += s_red[w2][4];
        }
        float npos = rcnt;
        float pw = ((float)NCELL - npos) / (npos + 1e-16f);
        float obj_b  = (rn + pw * rp) / (float)NCELL;
        float bbox_b = (npos > 0.0f) ? rb / (4.0f * npos + 1e-30f) : 0.0f;
        float cls_b  = (npos > 0.0f) ? rc / ((float)CC * npos + 1e-30f) : 0.0f;
        g_obj[b]  = obj_b;
        g_bbox[b] = bbox_b;
        g_cls[b]  = cls_b;
    }
}

__global__ void __launch_bounds__(256)
sgs_loss_reduce(float* __restrict__ out, int B)
{
    __shared__ double s_red[8][3];
    const int tid = threadIdx.x;
    double o = 0.0, bb = 0.0, cl = 0.0;
    for (int i = tid; i < B; i += 256) {        // coalesced SoA loads
        o  += (double)g_obj[i];
        bb += (double)g_bbox[i];
        cl += (double)g_cls[i];
    }
    #pragma unroll
    for (int off = 16; off > 0; off >>= 1) {
        o  += __shfl_down_sync(0xFFFFFFFFu, o,  off);
        bb += __shfl_down_sync(0xFFFFFFFFu, bb, off);
        cl += __shfl_down_sync(0xFFFFFFFFu, cl, off);
    }
    int wid = tid >> 5, lid = tid & 31;
    if (lid == 0) { s_red[wid][0] = o; s_red[wid][1] = bb; s_red[wid][2] = cl; }
    __syncthreads();
    if (tid == 0) {
        double ro = 0.0, rb = 0.0, rc = 0.0;
        #pragma unroll
        for (int w2 = 0; w2 < 8; w2++) {
            ro += s_red[w2][0]; rb += s_red[w2][1]; rc += s_red[w2][2];
        }
        float obj  = (float)(ro / (double)B);
        float bbox = (float)(rb / (double)B);
        float cls  = (float)(rc / (double)B);
        out[0] = 2.0f * obj + 5.0f * bbox + 2.0f * cls;
        out[1] = obj;
        out[2] = bbox;
        out[3] = cls;
    }
}

extern "C" void kernel_launch(void* const* d_in, const int* in_sizes, int n_in,
                              void* d_out, int out_size)
{
    const float*     pred    = (const float*)d_in[0];
    const float*     tboxes  = (const float*)d_in[1];
    const long long* tlabels = (const long long*)d_in[2];
    const float*     anchors = (const float*)d_in[3];
    float*           out     = (float*)d_out;

    int B = in_sizes[0] / (AA * CH * HW);
    if (B > BB) B = BB;

    sgs_loss_per_batch<<<B, 256>>>(pred, tboxes, tlabels, anchors);
    sgs_loss_reduce<<<1, 256>>>(out, B);
}